// round 13
// baseline (speedup 1.0000x reference)
#include <cuda_runtime.h>
#include <cuda_fp16.h>
#include <cstdint>

#define N_NODES 100000
#define N_EDGES 600000
#define HID 128
#define WSTRIDE 132                       // node fp32 tile stride (floats)
#define ERS 136                           // edge H row stride (halves), 272 B
#define SRS_B 528                         // staging row stride bytes: u 256 | v 256 | pad 16
#define NODE_TILES ((N_NODES + 63) / 64)  // 1563
#define EDGE_TILES (N_EDGES / 64)         // 9375 exact

// -------- device scratch --------
__device__ __align__(16) __half g_u[(size_t)N_NODES * HID];   // u + b1 folded
__device__ __align__(16) __half g_v[(size_t)N_NODES * HID];

// -------- helpers --------
__device__ __forceinline__ float totf32(float x) {
    float o; asm("cvt.rna.tf32.f32 %0, %1;" : "=f"(o) : "f"(x)); return o;
}
__device__ __forceinline__ float eluf(float v) {
    return v > 0.0f ? v : (__expf(v) - 1.0f);
}
__device__ __forceinline__ void mma8(float d[4], const uint32_t a[4], const uint32_t b[2]) {
    asm volatile(
        "mma.sync.aligned.m16n8k8.row.col.f32.tf32.tf32.f32 "
        "{%0,%1,%2,%3}, {%4,%5,%6,%7}, {%8,%9}, {%0,%1,%2,%3};"
        : "+f"(d[0]), "+f"(d[1]), "+f"(d[2]), "+f"(d[3])
        : "r"(a[0]), "r"(a[1]), "r"(a[2]), "r"(a[3]), "r"(b[0]), "r"(b[1]));
}
__device__ __forceinline__ void mma16(float d[4], uint32_t a0, uint32_t a1, uint32_t a2,
                                      uint32_t a3, uint32_t b0, uint32_t b1) {
    asm volatile(
        "mma.sync.aligned.m16n8k16.row.col.f32.f16.f16.f32 "
        "{%0,%1,%2,%3}, {%4,%5,%6,%7}, {%8,%9}, {%0,%1,%2,%3};"
        : "+f"(d[0]), "+f"(d[1]), "+f"(d[2]), "+f"(d[3])
        : "r"(a0), "r"(a1), "r"(a2), "r"(a3), "r"(b0), "r"(b1));
}
__device__ __forceinline__ void cp16(uint32_t dst, const void* src) {
    asm volatile("cp.async.cg.shared.global [%0], [%1], 16;" :: "r"(dst), "l"(src));
}
__device__ __forceinline__ uint32_t pack_h2(float lo, float hi) {
    __half2 h = __floats2half2_rn(lo, hi);
    return *(uint32_t*)&h;
}

// ================= node: u = x@W1u + b1, v = x@W1v ; fp16 out (self-prep W1) ====
#define NODE_SMEM_BYTES ((128 * WSTRIDE + 64 * WSTRIDE) * 4)   // 101376

__global__ __launch_bounds__(256, 2) void node_precompute(const float* __restrict__ x,
                                                          const float* __restrict__ W1,
                                                          const float* __restrict__ b1) {
    extern __shared__ float sm[];
    float* Ws = sm;                        // 128 x 132 (one W1 half, transposed, tf32)
    float* Xs = Ws + 128 * WSTRIDE;        // 64 x 132

    int half = blockIdx.x & 1;
    __half* dst = half ? g_v : g_u;

    int tid = threadIdx.x;
    // inline weight prep: Ws[n][k] = tf32(W1[k + half*128][n]); coalesced LDG over n
    for (int idx = tid; idx < 128 * 128; idx += 256) {
        int k = idx >> 7, n = idx & 127;
        Ws[n * WSTRIDE + k] = totf32(W1[(size_t)(k + half * 128) * 128 + n]);
    }

    int lane = tid & 31, wid = tid >> 5;
    int g = lane >> 2, tg = lane & 3;
    int wm = wid >> 2, wn = wid & 3;
    int row = tid >> 2, qq = tid & 3;

    float2 bb[4];
#pragma unroll
    for (int nt = 0; nt < 4; ++nt) {
        int c0 = wn * 32 + nt * 8 + 2 * tg;
        bb[nt] = half ? make_float2(0.f, 0.f) : *(const float2*)(b1 + c0);
    }

    for (int t = blockIdx.x >> 1; t < NODE_TILES; t += gridDim.x >> 1) {
        {
            int node = t * 64 + row;
            const float* xr = x + (size_t)(node < N_NODES ? node : 0) * HID;
#pragma unroll
            for (int j = 0; j < 8; ++j) {
                int col = j * 16 + qq * 4;
                float4 v = *(const float4*)(xr + col);
                v.x = totf32(v.x); v.y = totf32(v.y);
                v.z = totf32(v.z); v.w = totf32(v.w);
                *(float4*)(Xs + row * WSTRIDE + col) = v;
            }
        }
        __syncthreads();   // first iter: also covers Ws prep

        float acc[2][4][4];
#pragma unroll
        for (int i = 0; i < 2; ++i)
#pragma unroll
            for (int j = 0; j < 4; ++j)
#pragma unroll
                for (int l = 0; l < 4; ++l) acc[i][j][l] = 0.0f;

#pragma unroll
        for (int ks = 0; ks < 16; ++ks) {
            const int k0 = ks * 8;
            uint32_t a[2][4];
#pragma unroll
            for (int mt = 0; mt < 2; ++mt) {
                const float* p0 = Xs + (wm * 32 + mt * 16 + g) * WSTRIDE + k0 + tg;
                const float* p1 = p0 + 8 * WSTRIDE;
                a[mt][0] = __float_as_uint(p0[0]);
                a[mt][1] = __float_as_uint(p1[0]);
                a[mt][2] = __float_as_uint(p0[4]);
                a[mt][3] = __float_as_uint(p1[4]);
            }
            uint32_t b[4][2];
#pragma unroll
            for (int nt = 0; nt < 4; ++nt) {
                const float* q = Ws + (wn * 32 + nt * 8 + g) * WSTRIDE + k0 + tg;
                b[nt][0] = __float_as_uint(q[0]);
                b[nt][1] = __float_as_uint(q[4]);
            }
#pragma unroll
            for (int mt = 0; mt < 2; ++mt)
#pragma unroll
                for (int nt = 0; nt < 4; ++nt)
                    mma8(acc[mt][nt], a[mt], b[nt]);
        }

#pragma unroll
        for (int mt = 0; mt < 2; ++mt) {
            int r0 = t * 64 + wm * 32 + mt * 16 + g;
#pragma unroll
            for (int nt = 0; nt < 4; ++nt) {
                int c0 = wn * 32 + nt * 8 + 2 * tg;
                if (r0 < N_NODES)
                    *(__half2*)(dst + (size_t)r0 * HID + c0) =
                        __floats2half2_rn(acc[mt][nt][0] + bb[nt].x,
                                          acc[mt][nt][1] + bb[nt].y);
                if (r0 + 8 < N_NODES)
                    *(__half2*)(dst + (size_t)(r0 + 8) * HID + c0) =
                        __floats2half2_rn(acc[mt][nt][2] + bb[nt].x,
                                          acc[mt][nt][3] + bb[nt].y);
            }
        }
        __syncthreads();
    }
}

// ================= edge: cp.async gather ring -> fp16 GEMM (B in regs) =========
// smem: S0 33792 | S1 33792 | H0 17408 | H1 17408 | red 2048 | b2 512 | w3 512
#define S0_OFF  0
#define S1_OFF  33792
#define H0_OFF  67584
#define H1_OFF  84992
#define RED_OFF 102400
#define B2_OFF  104448
#define W3_OFF  104960
#define EDGE_SMEM_BYTES 105472

__device__ __forceinline__ void issue_gather(uint32_t sdst_base, const int* __restrict__ ei,
                                             int t, int row, int qq) {
    int e = t * 64 + row;
    if (e >= N_EDGES) e = N_EDGES - 1;
    int src = ei[e];
    int tgt = ei[N_EDGES + e];
    const char* up = (const char*)(g_u + (size_t)src * HID) + qq * 64;
    const char* vp = (const char*)(g_v + (size_t)tgt * HID) + qq * 64;
    uint32_t du = sdst_base + row * SRS_B + qq * 64;
    uint32_t dv = du + 256;
#pragma unroll
    for (int j = 0; j < 4; ++j) {
        cp16(du + j * 16, up + j * 16);
        cp16(dv + j * 16, vp + j * 16);
    }
    asm volatile("cp.async.commit_group;" ::: "memory");
}

__device__ __forceinline__ void convert_tile(const char* __restrict__ sstage,
                                             __half* __restrict__ Hrow, int row, int qq) {
    const __half2* su = (const __half2*)(sstage + row * SRS_B + qq * 64);
    const __half2* sv = (const __half2*)(sstage + row * SRS_B + 256 + qq * 64);
#pragma unroll
    for (int blk = 0; blk < 2; ++blk) {
        uint32_t h[8];
#pragma unroll
        for (int i = 0; i < 8; ++i) {
            float2 uf = __half22float2(su[blk * 8 + i]);
            float2 vf = __half22float2(sv[blk * 8 + i]);
            __half2 hv = __floats2half2_rn(eluf(uf.x + vf.x), eluf(uf.y + vf.y));
            h[i] = *(uint32_t*)&hv;
        }
        uint4* dst = (uint4*)(Hrow + (2 * qq + blk) * 16);
        dst[0] = make_uint4(h[0], h[4], h[1], h[5]);
        dst[1] = make_uint4(h[2], h[6], h[3], h[7]);
    }
}

__global__ __launch_bounds__(256, 2) void edge_mlp(
    const int* __restrict__ ei, const float* __restrict__ W2,
    const float* __restrict__ b2, const float* __restrict__ W3,
    const float* __restrict__ b3, float* __restrict__ out) {
    extern __shared__ char smc[];
    uint32_t sb = (uint32_t)__cvta_generic_to_shared(smc);
    __half* Hb[2] = {(__half*)(smc + H0_OFF), (__half*)(smc + H1_OFF)};
    const char* Sb[2] = {smc + S0_OFF, smc + S1_OFF};
    const uint32_t Ssb[2] = {sb + S0_OFF, sb + S1_OFF};
    float* redb = (float*)(smc + RED_OFF);
    float* b2s = (float*)(smc + B2_OFF);
    float* w3s = (float*)(smc + W3_OFF);

    int tid = threadIdx.x;
    int lane = tid & 31, wid = tid >> 5;
    int g = lane >> 2, tg = lane & 3;
    int wm = wid >> 2, wn = wid & 3;
    int row = tid >> 2, qq = tid & 3;
    int m0 = wm * 32, n0 = wn * 32;

    if (tid < 128) { b2s[tid] = b2[tid]; w3s[tid] = W3[tid]; }
    float bias3 = b3[0];

    // ---- B (W2) fragments -> 64 registers, loop-invariant ----
    uint32_t Br[8][4][2];
#pragma unroll
    for (int ks = 0; ks < 8; ++ks)
#pragma unroll
        for (int nt = 0; nt < 4; ++nt) {
            int n = n0 + nt * 8 + g;
            int k0 = ks * 16 + 2 * tg;
            Br[ks][nt][0] = pack_h2(W2[(size_t)k0 * 128 + n],
                                    W2[(size_t)(k0 + 1) * 128 + n]);
            Br[ks][nt][1] = pack_h2(W2[(size_t)(k0 + 8) * 128 + n],
                                    W2[(size_t)(k0 + 9) * 128 + n]);
        }

    // ---- prologue: prefetch first two tiles ----
    issue_gather(Ssb[0], ei, blockIdx.x, row, qq);
    issue_gather(Ssb[1], ei, blockIdx.x + gridDim.x, row, qq);

    int it = 0;
    int t = blockIdx.x;
    for (; t < EDGE_TILES; t += gridDim.x, ++it) {
        int cur = it & 1;

        // S[cur] complete (own bytes); convert to H[cur]
        asm volatile("cp.async.wait_group 1;" ::: "memory");
        convert_tile(Sb[cur], Hb[cur] + row * ERS, row, qq);
        // refill S[cur] with tile t + 2*grid (clamped inside)
        issue_gather(Ssb[cur], ei, t + 2 * (int)gridDim.x, row, qq);

        __syncthreads();   // H[cur] + red[prev] visible; it-2's MMA reads done

        // output tile t - grid from red[prev]
        if (it > 0 && tid < 64) {
            const float* rp = redb + ((cur ^ 1) << 8);
            out[(t - (int)gridDim.x) * 64 + tid] =
                rp[tid * 4 + 0] + rp[tid * 4 + 1] +
                rp[tid * 4 + 2] + rp[tid * 4 + 3] + bias3;
        }

        // ---- layer 2 MMA: H[cur] @ Br ----
        float acc[2][4][4];
#pragma unroll
        for (int i = 0; i < 2; ++i)
#pragma unroll
            for (int j = 0; j < 4; ++j)
#pragma unroll
                for (int l = 0; l < 4; ++l) acc[i][j][l] = 0.0f;

        const __half* Hc = Hb[cur];
#pragma unroll
        for (int ks = 0; ks < 8; ++ks) {
            int sc = ks * 16 + tg * 4;
            uint2 a0[2], a1[2];
#pragma unroll
            for (int mt = 0; mt < 2; ++mt) {
                a0[mt] = *(const uint2*)(Hc + (m0 + mt * 16 + g) * ERS + sc);
                a1[mt] = *(const uint2*)(Hc + (m0 + mt * 16 + 8 + g) * ERS + sc);
            }
#pragma unroll
            for (int mt = 0; mt < 2; ++mt)
#pragma unroll
                for (int nt = 0; nt < 4; ++nt)
                    mma16(acc[mt][nt], a0[mt].x, a1[mt].x, a0[mt].y, a1[mt].y,
                          Br[ks][nt][0], Br[ks][nt][1]);
        }

        // ---- layer 3: elu(acc + b2) . W3 ----
        float p0[2] = {0.f, 0.f}, p1[2] = {0.f, 0.f};
#pragma unroll
        for (int mt = 0; mt < 2; ++mt) {
#pragma unroll
            for (int nt = 0; nt < 4; ++nt) {
                int c0 = n0 + nt * 8 + 2 * tg;
                float2 w = *(const float2*)(w3s + c0);
                float2 bbv = *(const float2*)(b2s + c0);
                p0[mt] += eluf(acc[mt][nt][0] + bbv.x) * w.x +
                          eluf(acc[mt][nt][1] + bbv.y) * w.y;
                p1[mt] += eluf(acc[mt][nt][2] + bbv.x) * w.x +
                          eluf(acc[mt][nt][3] + bbv.y) * w.y;
            }
        }
#pragma unroll
        for (int mt = 0; mt < 2; ++mt) {
            p0[mt] += __shfl_xor_sync(0xffffffffu, p0[mt], 1);
            p0[mt] += __shfl_xor_sync(0xffffffffu, p0[mt], 2);
            p1[mt] += __shfl_xor_sync(0xffffffffu, p1[mt], 1);
            p1[mt] += __shfl_xor_sync(0xffffffffu, p1[mt], 2);
        }
        if (tg == 0) {
            float* rc = redb + (cur << 8);
#pragma unroll
            for (int mt = 0; mt < 2; ++mt) {
                int rl = m0 + mt * 16 + g;
                rc[rl * 4 + wn] = p0[mt];
                rc[(rl + 8) * 4 + wn] = p1[mt];
            }
        }
    }

    // drain: final tile's output
    __syncthreads();
    {
        const float* rp = redb + (((it - 1) & 1) << 8);
        if (tid < 64)
            out[(t - (int)gridDim.x) * 64 + tid] =
                rp[tid * 4 + 0] + rp[tid * 4 + 1] +
                rp[tid * 4 + 2] + rp[tid * 4 + 3] + bias3;
    }
}

// ================= launch =================
extern "C" void kernel_launch(void* const* d_in, const int* in_sizes, int n_in,
                              void* d_out, int out_size) {
    const float* x  = (const float*)d_in[0];
    const int*   ei = (const int*)d_in[1];
    const float* W1 = (const float*)d_in[2];
    const float* b1 = (const float*)d_in[3];
    const float* W2 = (const float*)d_in[4];
    const float* b2 = (const float*)d_in[5];
    const float* W3 = (const float*)d_in[6];
    const float* b3 = (const float*)d_in[7];
    float* out = (float*)d_out;

    cudaFuncSetAttribute(node_precompute,
                         cudaFuncAttributeMaxDynamicSharedMemorySize, NODE_SMEM_BYTES);
    cudaFuncSetAttribute(edge_mlp,
                         cudaFuncAttributeMaxDynamicSharedMemorySize, EDGE_SMEM_BYTES);

    node_precompute<<<296, 256, NODE_SMEM_BYTES>>>(x, W1, b1);
    edge_mlp<<<296, 256, EDGE_SMEM_BYTES>>>(ei, W2, b2, W3, b3, out);
}

// round 14
// speedup vs baseline: 1.5340x; 1.5340x over previous
#include <cuda_runtime.h>
#include <cuda_fp16.h>
#include <cstdint>

#define N_NODES 100000
#define N_EDGES 600000
#define HID 128
#define ERS 144                           // fp16 row stride (halves) = 288 B, conflict-free
#define NODE_TILES ((N_NODES + 63) / 64)  // 1563
#define EDGE_TILES (N_EDGES / 64)         // 9375 exact

// -------- device scratch --------
__device__ __align__(16) __half g_u[(size_t)N_NODES * HID];   // u + b1 folded
__device__ __align__(16) __half g_v[(size_t)N_NODES * HID];

// -------- helpers --------
__device__ __forceinline__ float eluf(float v) {
    return v > 0.0f ? v : (__expf(v) - 1.0f);
}
__device__ __forceinline__ int p16(int k) {
    int blk = k >> 4, o = k & 15;
    int t = (o & 7) >> 1;
    int pos = (o < 8) ? (4 * t + (o & 1)) : (4 * t + 2 + (o & 1));
    return blk * 16 + pos;
}
__device__ __forceinline__ uint32_t pack_h2(float lo, float hi) {
    __half2 h = __floats2half2_rn(lo, hi);
    return *(uint32_t*)&h;
}
__device__ __forceinline__ void mma16(float d[4], uint32_t a0, uint32_t a1, uint32_t a2,
                                      uint32_t a3, uint32_t b0, uint32_t b1) {
    asm volatile(
        "mma.sync.aligned.m16n8k16.row.col.f32.f16.f16.f32 "
        "{%0,%1,%2,%3}, {%4,%5,%6,%7}, {%8,%9}, {%0,%1,%2,%3};"
        : "+f"(d[0]), "+f"(d[1]), "+f"(d[2]), "+f"(d[3])
        : "r"(a0), "r"(a1), "r"(a2), "r"(a3), "r"(b0), "r"(b1));
}

// shared MMA tile: acc[2][4][4] += A[64][128] @ B[128][128]^T, both permuted fp16 @ERS
__device__ __forceinline__ void mma_tile(const __half* __restrict__ As,
                                         const __half* __restrict__ Bs,
                                         float acc[2][4][4],
                                         int m0, int n0, int g, int tg) {
#pragma unroll
    for (int ks = 0; ks < 8; ++ks) {
        int sc = ks * 16 + tg * 4;
        uint2 a0[2], a1[2];
#pragma unroll
        for (int mt = 0; mt < 2; ++mt) {
            a0[mt] = *(const uint2*)(As + (m0 + mt * 16 + g) * ERS + sc);
            a1[mt] = *(const uint2*)(As + (m0 + mt * 16 + 8 + g) * ERS + sc);
        }
        uint2 bq[4];
#pragma unroll
        for (int nt = 0; nt < 4; ++nt)
            bq[nt] = *(const uint2*)(Bs + (n0 + nt * 8 + g) * ERS + sc);
#pragma unroll
        for (int mt = 0; mt < 2; ++mt)
#pragma unroll
            for (int nt = 0; nt < 4; ++nt)
                mma16(acc[mt][nt], a0[mt].x, a1[mt].x, a0[mt].y, a1[mt].y,
                      bq[nt].x, bq[nt].y);
    }
}

// ================= node: u = x@W1u + b1, v = x@W1v ; fp16 MMA =================
#define NODE_SMEM_BYTES ((128 * ERS + 64 * ERS) * 2)   // 55296

__global__ __launch_bounds__(256, 3) void node_precompute(const float* __restrict__ x,
                                                          const float* __restrict__ W1,
                                                          const float* __restrict__ b1) {
    extern __shared__ char smc[];
    __half* Ws = (__half*)smc;            // 128 x 144 permuted fp16 (one W1 half)
    __half* Xs = Ws + 128 * ERS;          // 64 x 144 permuted fp16

    int half = blockIdx.x & 1;
    __half* dst = half ? g_v : g_u;

    int tid = threadIdx.x;
    // inline W prep (coalesced over n)
    for (int idx = tid; idx < 128 * 128; idx += 256) {
        int k = idx >> 7, n = idx & 127;
        Ws[n * ERS + p16(k)] = __float2half(W1[(size_t)(k + half * 128) * 128 + n]);
    }

    int lane = tid & 31, wid = tid >> 5;
    int g = lane >> 2, tg = lane & 3;
    int wm = wid >> 2, wn = wid & 3;
    int row = tid >> 2, qq = tid & 3;
    int m0 = wm * 32, n0 = wn * 32;

    float2 bb[4];
#pragma unroll
    for (int nt = 0; nt < 4; ++nt) {
        int c0 = n0 + nt * 8 + 2 * tg;
        bb[nt] = half ? make_float2(0.f, 0.f) : *(const float2*)(b1 + c0);
    }

    int step = gridDim.x >> 1;
    for (int t = blockIdx.x >> 1; t < NODE_TILES; t += step) {
        // stage x tile -> permuted fp16
        {
            int node = t * 64 + row;
            if (node >= N_NODES) node = N_NODES - 1;
            const float* xr = x + (size_t)node * HID + qq * 32;
#pragma unroll
            for (int blk = 0; blk < 2; ++blk) {
                uint32_t h[8];
#pragma unroll
                for (int j = 0; j < 4; ++j) {
                    float4 v = *(const float4*)(xr + blk * 16 + j * 4);
                    h[2 * j] = pack_h2(v.x, v.y);
                    h[2 * j + 1] = pack_h2(v.z, v.w);
                }
                uint4* dp = (uint4*)(Xs + row * ERS + (2 * qq + blk) * 16);
                dp[0] = make_uint4(h[0], h[4], h[1], h[5]);
                dp[1] = make_uint4(h[2], h[6], h[3], h[7]);
            }
        }
        __syncthreads();   // first iter also covers Ws prep

        float acc[2][4][4];
#pragma unroll
        for (int i = 0; i < 2; ++i)
#pragma unroll
            for (int j = 0; j < 4; ++j)
#pragma unroll
                for (int l = 0; l < 4; ++l) acc[i][j][l] = 0.0f;

        mma_tile(Xs, Ws, acc, m0, n0, g, tg);

#pragma unroll
        for (int mt = 0; mt < 2; ++mt) {
            int r0 = t * 64 + m0 + mt * 16 + g;
#pragma unroll
            for (int nt = 0; nt < 4; ++nt) {
                int c0 = n0 + nt * 8 + 2 * tg;
                if (r0 < N_NODES)
                    *(__half2*)(dst + (size_t)r0 * HID + c0) =
                        __floats2half2_rn(acc[mt][nt][0] + bb[nt].x,
                                          acc[mt][nt][1] + bb[nt].y);
                if (r0 + 8 < N_NODES)
                    *(__half2*)(dst + (size_t)(r0 + 8) * HID + c0) =
                        __floats2half2_rn(acc[mt][nt][2] + bb[nt].x,
                                          acc[mt][nt][3] + bb[nt].y);
            }
        }
        __syncthreads();
    }
}

// ================= edge: pipelined gather -> fp16 GEMM -> elu + W3 dot =========
// smem: W2s 36864 | H 18432 | red 2x1024 | b2 512 | w3 512 = 58368 -> 3 CTAs/SM
#define W2S_OFF 0
#define HS_OFF  36864
#define RED_OFF 55296
#define B2_OFF  57344
#define W3_OFF  57856
#define EDGE_SMEM_BYTES 58368

__device__ __forceinline__ void gather_regs(uint4 U[4], uint4 V[4],
                                            const int* __restrict__ ei,
                                            int t, int row, int qq) {
    int e = t * 64 + row;
    if (e >= N_EDGES) e = N_EDGES - 1;
    int src = ei[e];
    int tgt = ei[N_EDGES + e];
    const uint4* up = ((const uint4*)(g_u + (size_t)src * HID)) + 4 * qq;
    const uint4* vp = ((const uint4*)(g_v + (size_t)tgt * HID)) + 4 * qq;
#pragma unroll
    for (int i = 0; i < 4; ++i) { U[i] = up[i]; V[i] = vp[i]; }
}

__device__ __forceinline__ void convert_store(__half* __restrict__ Hrow, int qq,
                                              const uint4 U[4], const uint4 V[4]) {
    const __half2* uh = (const __half2*)U;
    const __half2* vh = (const __half2*)V;
#pragma unroll
    for (int blk = 0; blk < 2; ++blk) {
        uint32_t h[8];
#pragma unroll
        for (int i = 0; i < 8; ++i) {
            float2 uf = __half22float2(uh[blk * 8 + i]);
            float2 vf = __half22float2(vh[blk * 8 + i]);
            h[i] = pack_h2(eluf(uf.x + vf.x), eluf(uf.y + vf.y));
        }
        uint4* dst = (uint4*)(Hrow + (2 * qq + blk) * 16);
        dst[0] = make_uint4(h[0], h[4], h[1], h[5]);
        dst[1] = make_uint4(h[2], h[6], h[3], h[7]);
    }
}

__global__ __launch_bounds__(256, 3) void edge_mlp(
    const int* __restrict__ ei, const float* __restrict__ W2,
    const float* __restrict__ b2, const float* __restrict__ W3,
    const float* __restrict__ b3, float* __restrict__ out) {
    extern __shared__ char smc[];
    __half* W2s = (__half*)(smc + W2S_OFF);
    __half* Hs  = (__half*)(smc + HS_OFF);
    float* redb = (float*)(smc + RED_OFF);   // 2 x 64 x 4
    float* b2s = (float*)(smc + B2_OFF);
    float* w3s = (float*)(smc + W3_OFF);

    int tid = threadIdx.x;
    // inline W2 prep (coalesced over n)
    for (int idx = tid; idx < 128 * 128; idx += 256) {
        int k = idx >> 7, n = idx & 127;
        W2s[n * ERS + p16(k)] = __float2half(W2[(size_t)k * 128 + n]);
    }
    if (tid < 128) { b2s[tid] = b2[tid]; w3s[tid] = W3[tid]; }
    float bias3 = b3[0];

    int lane = tid & 31, wid = tid >> 5;
    int g = lane >> 2, tg = lane & 3;
    int wm = wid >> 2, wn = wid & 3;
    int row = tid >> 2, qq = tid & 3;
    int m0 = wm * 32, n0 = wn * 32;

    // prologue: gather first tile into registers
    uint4 U[4], V[4];
    gather_regs(U, V, ei, blockIdx.x, row, qq);

    int it = 0;
    int t = blockIdx.x;
    for (; t < EDGE_TILES; t += gridDim.x, ++it) {
        int cur = it & 1;

        // 1. convert current regs -> H (H free: prior iter's tail sync)
        convert_store(Hs + row * ERS, qq, U, V);
        // 2. prefetch next tile into regs (overlaps this iter's MMA)
        gather_regs(U, V, ei, t + (int)gridDim.x, row, qq);

        __syncthreads();   // H (+ first-iter W2s/b2s/w3s) visible

        // 3. output for tile t-grid from the other red buffer
        if (it > 0 && tid < 64) {
            const float* rp = redb + ((cur ^ 1) << 8);
            out[(t - (int)gridDim.x) * 64 + tid] =
                rp[tid * 4 + 0] + rp[tid * 4 + 1] +
                rp[tid * 4 + 2] + rp[tid * 4 + 3] + bias3;
        }

        // 4. layer-2 MMA
        float acc[2][4][4];
#pragma unroll
        for (int i = 0; i < 2; ++i)
#pragma unroll
            for (int j = 0; j < 4; ++j)
#pragma unroll
                for (int l = 0; l < 4; ++l) acc[i][j][l] = 0.0f;

        mma_tile(Hs, W2s, acc, m0, n0, g, tg);

        // 5. layer 3: elu(acc + b2) . W3 -> red[cur]
        float p0[2] = {0.f, 0.f}, p1[2] = {0.f, 0.f};
#pragma unroll
        for (int mt = 0; mt < 2; ++mt) {
#pragma unroll
            for (int nt = 0; nt < 4; ++nt) {
                int c0 = n0 + nt * 8 + 2 * tg;
                float2 w = *(const float2*)(w3s + c0);
                float2 bv = *(const float2*)(b2s + c0);
                p0[mt] += eluf(acc[mt][nt][0] + bv.x) * w.x +
                          eluf(acc[mt][nt][1] + bv.y) * w.y;
                p1[mt] += eluf(acc[mt][nt][2] + bv.x) * w.x +
                          eluf(acc[mt][nt][3] + bv.y) * w.y;
            }
        }
#pragma unroll
        for (int mt = 0; mt < 2; ++mt) {
            p0[mt] += __shfl_xor_sync(0xffffffffu, p0[mt], 1);
            p0[mt] += __shfl_xor_sync(0xffffffffu, p0[mt], 2);
            p1[mt] += __shfl_xor_sync(0xffffffffu, p1[mt], 1);
            p1[mt] += __shfl_xor_sync(0xffffffffu, p1[mt], 2);
        }
        if (tg == 0) {
            float* rc = redb + (cur << 8);
#pragma unroll
            for (int mt = 0; mt < 2; ++mt) {
                int rl = m0 + mt * 16 + g;
                rc[rl * 4 + wn] = p0[mt];
                rc[(rl + 8) * 4 + wn] = p1[mt];
            }
        }
        __syncthreads();   // MMA reads done (H reusable); red[cur] visible
    }

    // drain: final tile's output
    {
        const float* rp = redb + (((it - 1) & 1) << 8);
        if (tid < 64)
            out[(t - (int)gridDim.x) * 64 + tid] =
                rp[tid * 4 + 0] + rp[tid * 4 + 1] +
                rp[tid * 4 + 2] + rp[tid * 4 + 3] + bias3;
    }
}

// ================= launch =================
extern "C" void kernel_launch(void* const* d_in, const int* in_sizes, int n_in,
                              void* d_out, int out_size) {
    const float* x  = (const float*)d_in[0];
    const int*   ei = (const int*)d_in[1];
    const float* W1 = (const float*)d_in[2];
    const float* b1 = (const float*)d_in[3];
    const float* W2 = (const float*)d_in[4];
    const float* b2 = (const float*)d_in[5];
    const float* W3 = (const float*)d_in[6];
    const float* b3 = (const float*)d_in[7];
    float* out = (float*)d_out;

    cudaFuncSetAttribute(node_precompute,
                         cudaFuncAttributeMaxDynamicSharedMemorySize, NODE_SMEM_BYTES);
    cudaFuncSetAttribute(edge_mlp,
                         cudaFuncAttributeMaxDynamicSharedMemorySize, EDGE_SMEM_BYTES);

    node_precompute<<<444, 256, NODE_SMEM_BYTES>>>(x, W1, b1);
    edge_mlp<<<444, 256, EDGE_SMEM_BYTES>>>(ei, W2, b2, W3, b3, out);
}